// round 16
// baseline (speedup 1.0000x reference)
#include <cuda_runtime.h>
#include <cuda_fp16.h>
#include <math.h>

#define N_MAX  (128 * 128 * 128)
#define T_MAX  4194304u
#define TPB    256

// Static scratch (no allocations). Zero-initialized at module load.
// Invariant across graph replays: g_cntp is zero at k_hash_count entry
// (k_main re-zeros it each call), g_sum/g_sumsq/g_done are zero at
// k_transpose entry (its last-done block resets them).
__device__ unsigned g_cntp[T_MAX / 4];             // 4 MB  byte-packed ref counts
__device__ uint4    g_rec[(size_t)T_MAX * 2];      // 134 MB fp16 records (32B/entry)
__device__ double   g_sum, g_sumsq;
__device__ unsigned g_done;
__device__ float2   g_stats;                       // x = mean, y = (2*far/vs/6)/std

__device__ __forceinline__ unsigned hash_idx(unsigned c0, unsigned c1, unsigned c2,
                                             unsigned tsize) {
    unsigned h = (c0 * 1u) ^ (c1 * 2654435761u) ^ (c2 * 805459861u);
    return h % tsize;
}

__device__ __forceinline__ float sigmoidf_(float x) {
    return __fdividef(1.0f, 1.0f + __expf(-x));
}

__device__ __forceinline__ unsigned pack2(float a, float b) {
    __half2 h = __floats2half2_rn(a, b);
    return *(unsigned*)&h;
}

// Hash 4 points/thread; byte-packed histogram (no-return atomics).
__global__ void __launch_bounds__(TPB) k_hash_count(const int* __restrict__ coords,
                                                    int n, unsigned tsize) {
    int i0 = (blockIdx.x * TPB + threadIdx.x) * 4;
    if (i0 + 3 < n) {
        const int4* cp = (const int4*)(coords + (size_t)i0 * 3);
        int4 a = __ldg(cp + 0);
        int4 b = __ldg(cp + 1);
        int4 c = __ldg(cp + 2);
        unsigned i0x = hash_idx((unsigned)a.x, (unsigned)a.y, (unsigned)a.z, tsize);
        unsigned i1x = hash_idx((unsigned)a.w, (unsigned)b.x, (unsigned)b.y, tsize);
        unsigned i2x = hash_idx((unsigned)b.z, (unsigned)b.w, (unsigned)c.x, tsize);
        unsigned i3x = hash_idx((unsigned)c.y, (unsigned)c.z, (unsigned)c.w, tsize);
        atomicAdd(&g_cntp[i0x >> 2], 1u << ((i0x & 3u) * 8u));
        atomicAdd(&g_cntp[i1x >> 2], 1u << ((i1x & 3u) * 8u));
        atomicAdd(&g_cntp[i2x >> 2], 1u << ((i2x & 3u) * 8u));
        atomicAdd(&g_cntp[i3x >> 2], 1u << ((i3x & 3u) * 8u));
    } else {
        for (int i = i0; i < n; i++) {
            unsigned c0 = (unsigned)coords[3 * i + 0];
            unsigned c1 = (unsigned)coords[3 * i + 1];
            unsigned c2 = (unsigned)coords[3 * i + 2];
            unsigned idx = hash_idx(c0, c1, c2, tsize);
            atomicAdd(&g_cntp[idx >> 2], 1u << ((idx & 3u) * 8u));
        }
    }
}

// Streaming SoA->AoS(fp16) transpose fused with the fp32 stats reduction.
// Record layout (16 halves / 32B per entry):
//   pair0: dm0 dm1 | pair1: dm2 q0 | pair2: q1 q2 | pair3: q3 s0
//   pair4: s1 s2   | pair5: h0 h1  | pair6: h2 od | pair7: 0 0
__global__ void __launch_bounds__(TPB) k_transpose(const float* __restrict__ table,
                                                   const float* __restrict__ far_p,
                                                   const int* __restrict__ vs_p,
                                                   unsigned tsize, int n) {
    unsigned t  = threadIdx.x;
    unsigned e4 = blockIdx.x * TPB + t;          // group of 4 entries
    unsigned e  = e4 * 4;

    unsigned cw = g_cntp[e4];
    bool bx = (cw & 0xFFu)        != 0u;
    bool by = (cw & 0xFF00u)      != 0u;
    bool bz = (cw & 0xFF0000u)    != 0u;
    bool bw = (cw & 0xFF000000u)  != 0u;

    uint2* rec = (uint2*)(g_rec + (size_t)e * 2);   // 4 uint2 per entry
    float s = 0.0f, ss = 0.0f;

    // quad 0: rows 0-3 (stats from rows 0-2)
    {
        float4 v0 = __ldcs((const float4*)(table + 0 * (size_t)tsize) + e4);
        float4 v1 = __ldcs((const float4*)(table + 1 * (size_t)tsize) + e4);
        float4 v2 = __ldcs((const float4*)(table + 2 * (size_t)tsize) + e4);
        float4 v3 = __ldcs((const float4*)(table + 3 * (size_t)tsize) + e4);
        float f0 = (float)(cw & 0xFFu);
        float f1 = (float)((cw >> 8) & 0xFFu);
        float f2 = (float)((cw >> 16) & 0xFFu);
        float f3 = (float)(cw >> 24);
        s  = f0 * (v0.x + v1.x + v2.x) + f1 * (v0.y + v1.y + v2.y)
           + f2 * (v0.z + v1.z + v2.z) + f3 * (v0.w + v1.w + v2.w);
        ss = f0 * (v0.x * v0.x + v1.x * v1.x + v2.x * v2.x)
           + f1 * (v0.y * v0.y + v1.y * v1.y + v2.y * v2.y)
           + f2 * (v0.z * v0.z + v1.z * v1.z + v2.z * v2.z)
           + f3 * (v0.w * v0.w + v1.w * v1.w + v2.w * v2.w);
        if (bx) rec[0]  = make_uint2(pack2(v0.x, v1.x), pack2(v2.x, v3.x));
        if (by) rec[4]  = make_uint2(pack2(v0.y, v1.y), pack2(v2.y, v3.y));
        if (bz) rec[8]  = make_uint2(pack2(v0.z, v1.z), pack2(v2.z, v3.z));
        if (bw) rec[12] = make_uint2(pack2(v0.w, v1.w), pack2(v2.w, v3.w));
    }
    // quad 1: rows 4-7
    {
        float4 v0 = __ldcs((const float4*)(table + 4 * (size_t)tsize) + e4);
        float4 v1 = __ldcs((const float4*)(table + 5 * (size_t)tsize) + e4);
        float4 v2 = __ldcs((const float4*)(table + 6 * (size_t)tsize) + e4);
        float4 v3 = __ldcs((const float4*)(table + 7 * (size_t)tsize) + e4);
        if (bx) rec[1]  = make_uint2(pack2(v0.x, v1.x), pack2(v2.x, v3.x));
        if (by) rec[5]  = make_uint2(pack2(v0.y, v1.y), pack2(v2.y, v3.y));
        if (bz) rec[9]  = make_uint2(pack2(v0.z, v1.z), pack2(v2.z, v3.z));
        if (bw) rec[13] = make_uint2(pack2(v0.w, v1.w), pack2(v2.w, v3.w));
    }
    // quad 2: rows 8-11
    {
        float4 v0 = __ldcs((const float4*)(table + 8  * (size_t)tsize) + e4);
        float4 v1 = __ldcs((const float4*)(table + 9  * (size_t)tsize) + e4);
        float4 v2 = __ldcs((const float4*)(table + 10 * (size_t)tsize) + e4);
        float4 v3 = __ldcs((const float4*)(table + 11 * (size_t)tsize) + e4);
        if (bx) rec[2]  = make_uint2(pack2(v0.x, v1.x), pack2(v2.x, v3.x));
        if (by) rec[6]  = make_uint2(pack2(v0.y, v1.y), pack2(v2.y, v3.y));
        if (bz) rec[10] = make_uint2(pack2(v0.z, v1.z), pack2(v2.z, v3.z));
        if (bw) rec[14] = make_uint2(pack2(v0.w, v1.w), pack2(v2.w, v3.w));
    }
    // quad 3: rows 12-13
    {
        float4 v0 = __ldcs((const float4*)(table + 12 * (size_t)tsize) + e4);
        float4 v1 = __ldcs((const float4*)(table + 13 * (size_t)tsize) + e4);
        if (bx) rec[3]  = make_uint2(pack2(v0.x, v1.x), 0u);
        if (by) rec[7]  = make_uint2(pack2(v0.y, v1.y), 0u);
        if (bz) rec[11] = make_uint2(pack2(v0.z, v1.z), 0u);
        if (bw) rec[15] = make_uint2(pack2(v0.w, v1.w), 0u);
    }

    // block stats reduction -> double atomics
    double ds = (double)s, dss = (double)ss;
    #pragma unroll
    for (int o = 16; o > 0; o >>= 1) {
        ds  += __shfl_down_sync(0xFFFFFFFFu, ds,  o);
        dss += __shfl_down_sync(0xFFFFFFFFu, dss, o);
    }
    __shared__ double sh_s[8], sh_ss[8];
    int lane = t & 31, w = t >> 5;
    if (lane == 0) { sh_s[w] = ds; sh_ss[w] = dss; }
    __syncthreads();
    if (t == 0) {
        double ts = 0.0, tss = 0.0;
        for (int k = 0; k < TPB / 32; k++) { ts += sh_s[k]; tss += sh_ss[k]; }
        atomicAdd(&g_sum, ts);
        atomicAdd(&g_sumsq, tss);
        __threadfence();
        unsigned done = atomicAdd(&g_done, 1u);
        if (done == gridDim.x - 1u) {
            double M    = 3.0 * (double)n;
            double mean = g_sum / M;
            double var  = (g_sumsq - g_sum * g_sum / M) / (M - 1.0);  // ddof=1
            float stdv  = (float)sqrt(var);
            float f     = __ldg(far_p);
            float vs    = (float)__ldg(vs_p);
            float a     = 2.0f * f / vs;
            g_stats = make_float2((float)mean, a / (6.0f * stdv));
            // reset accumulators for the next graph replay (one thread, cheap)
            g_sum = 0.0; g_sumsq = 0.0; g_done = 0u;
        }
    }
}

// Main pass. Each point owns a 20-word smem slot:
//   phase A: 2-lane cooperative fetch of the 32B fp16 record into words 0-7
//   phase B: thread t converts+computes, writes 16 fp32 outputs IN PLACE
//   phase C: coalesced scalar __stcs stores from strided smem
// Tail: blocks 0..tsize/4/TPB-1 re-zero the count array for the next replay.
__global__ void __launch_bounds__(TPB, 8) k_main(const int* __restrict__ coords,
                                                 const float* __restrict__ cam,
                                                 const float* __restrict__ far_p,
                                                 const int* __restrict__ vs_p,
                                                 float* __restrict__ out,
                                                 int n, unsigned tsize) {
    __shared__ int sh_co[TPB * 3];                        // 3 KB coords
    __shared__ __align__(16) float slot[TPB * 20];        // 20 KB slots

    int t  = threadIdx.x;
    int p0 = blockIdx.x * TPB;
    int blk = min(TPB, n - p0);

    if (blk == TPB) {
        if (t < TPB * 3 / 4)
            ((int4*)sh_co)[t] = __ldg((const int4*)(coords + (size_t)p0 * 3) + t);
    } else {
        for (int k = t; k < blk * 3; k += TPB)
            sh_co[k] = coords[(size_t)p0 * 3 + k];
    }
    __syncthreads();

    // phase A: pair of lanes per point fetch the 32B record
    int gid = t >> 1, q = t & 1;
    #pragma unroll
    for (int it = 0; it < 2; it++) {
        int pl = it * 128 + gid;
        if (pl < blk) {
            unsigned idx = hash_idx((unsigned)sh_co[pl * 3 + 0],
                                    (unsigned)sh_co[pl * 3 + 1],
                                    (unsigned)sh_co[pl * 3 + 2], tsize);
            *(uint4*)(slot + pl * 20 + q * 4) = __ldg(g_rec + (size_t)idx * 2 + q);
        }
    }
    __syncthreads();

    if (t < blk) {
        float* sl = slot + t * 20;
        const __half2* hp = (const __half2*)sl;
        float2 p0v = __half22float2(hp[0]);   // dm0 dm1
        float2 p1v = __half22float2(hp[1]);   // dm2 q0
        float2 p2v = __half22float2(hp[2]);   // q1 q2
        float2 p3v = __half22float2(hp[3]);   // q3 s0
        float2 p4v = __half22float2(hp[4]);   // s1 s2
        float2 p5v = __half22float2(hp[5]);   // h0 h1
        float2 p6v = __half22float2(hp[6]);   // h2 od

        float f  = __ldg(far_p);
        float vs = (float)__ldg(vs_p);
        float a  = 2.0f * f / vs;
        float off = -f + f / vs;
        float2 st = g_stats;

        int c0 = sh_co[t * 3 + 0];
        int c1 = sh_co[t * 3 + 1];
        int c2 = sh_co[t * 3 + 2];

        sl[0] = (p0v.x - st.x) * st.y + (float)c0 * a + __ldg(cam + 0) + off;
        sl[1] = (p0v.y - st.x) * st.y + (float)c1 * a + __ldg(cam + 1) + off;
        sl[2] = (p1v.x - st.x) * st.y + (float)c2 * a + __ldg(cam + 2) + off;

        float q0 = p1v.y, q1 = p2v.x, q2 = p2v.y, q3 = p3v.x;
        float rn = rsqrtf(q0 * q0 + q1 * q1 + q2 * q2 + q3 * q3);
        float r = q0 * rn, x = q1 * rn, y = q2 * rn, z = q3 * rn;
        float R00 = 1.0f - 2.0f * (y * y + z * z);
        float R01 = 2.0f * (x * y - r * z);
        float R02 = 2.0f * (x * z + r * y);
        float R10 = 2.0f * (x * y + r * z);
        float R11 = 1.0f - 2.0f * (x * x + z * z);
        float R12 = 2.0f * (y * z - r * x);
        float R20 = 2.0f * (x * z - r * y);
        float R21 = 2.0f * (y * z + r * x);
        float R22 = 1.0f - 2.0f * (x * x + y * y);

        float sc0 = sigmoidf_(p3v.y) * a;
        float sc1 = sigmoidf_(p4v.x) * a;
        float sc2 = sigmoidf_(p4v.y) * a;
        float v0 = sc0 * sc0, v1 = sc1 * sc1, v2 = sc2 * sc2;

        float c01 = R00 * R10 * v0 + R01 * R11 * v1 + R02 * R12 * v2;
        float c02 = R00 * R20 * v0 + R01 * R21 * v1 + R02 * R22 * v2;
        float c12 = R10 * R20 * v0 + R11 * R21 * v1 + R12 * R22 * v2;
        sl[3]  = R00 * R00 * v0 + R01 * R01 * v1 + R02 * R02 * v2;
        sl[4]  = c01; sl[5] = c02;
        sl[6]  = c01;
        sl[7]  = R10 * R10 * v0 + R11 * R11 * v1 + R12 * R12 * v2;
        sl[8]  = c12;
        sl[9]  = c02; sl[10] = c12;
        sl[11] = R20 * R20 * v0 + R21 * R21 * v1 + R22 * R22 * v2;

        sl[12] = p5v.x;
        sl[13] = p5v.y;
        sl[14] = p6v.x;
        sl[15] = sigmoidf_(p6v.y - 4.0f);
    }
    __syncthreads();

    float* means = out;
    float* cov   = out + 3  * (size_t)n;
    float* harm  = out + 12 * (size_t)n;
    float* opac  = out + 15 * (size_t)n;

    for (int k = t; k < blk * 3; k += TPB)
        __stcs(means + (size_t)p0 * 3 + k, slot[(k / 3) * 20 + (k % 3)]);
    for (int k = t; k < blk * 9; k += TPB)
        __stcs(cov + (size_t)p0 * 9 + k, slot[(k / 9) * 20 + 3 + (k % 9)]);
    for (int k = t; k < blk * 3; k += TPB)
        __stcs(harm + (size_t)p0 * 3 + k, slot[(k / 3) * 20 + 12 + (k % 3)]);
    if (t < blk)
        __stcs(opac + p0 + t, slot[t * 20 + 15]);

    // tail: re-zero the packed counts for the next graph replay
    unsigned zi = blockIdx.x * (unsigned)TPB + (unsigned)t;
    if (zi < tsize / 4)
        __stcs(&g_cntp[zi], 0u);
}

extern "C" void kernel_launch(void* const* d_in, const int* in_sizes, int n_in,
                              void* d_out, int out_size) {
    const int*   coords = (const int*)d_in[0];
    const float* table  = (const float*)d_in[1];
    const float* cam    = (const float*)d_in[2];
    const float* far_p  = (const float*)d_in[3];
    const int*   vs_p   = (const int*)d_in[4];
    float*       out    = (float*)d_out;

    int n = in_sizes[0] / 3;
    unsigned tsize = (unsigned)(in_sizes[1] / 14);   // 4194304 for this problem

    int pblocks = (n + TPB - 1) / TPB;
    int hblocks = (n / 4 + TPB - 1) / TPB;
    int tblocks = (int)((tsize / 4 + TPB - 1) / TPB);

    k_hash_count<<<hblocks, TPB>>>(coords, n, tsize);
    k_transpose <<<tblocks, TPB>>>(table, far_p, vs_p, tsize, n);
    k_main      <<<pblocks, TPB>>>(coords, cam, far_p, vs_p, out, n, tsize);
}

// round 17
// speedup vs baseline: 1.1484x; 1.1484x over previous
#include <cuda_runtime.h>
#include <cuda_fp16.h>
#include <math.h>

#define N_MAX  (128 * 128 * 128)
#define T_MAX  4194304u
#define TPB    256

// Static scratch (no allocations).
__device__ unsigned g_cntp[T_MAX / 4];             // 4 MB  byte-packed ref counts
__device__ uint4    g_rec[(size_t)T_MAX * 2];      // 134 MB fp16 records (32B/entry)
__device__ double   g_sum, g_sumsq;
__device__ unsigned g_done;
__device__ float2   g_stats;                       // x = mean, y = (2*far/vs/6)/std

__device__ __forceinline__ unsigned hash_idx(unsigned c0, unsigned c1, unsigned c2,
                                             unsigned tsize) {
    unsigned h = (c0 * 1u) ^ (c1 * 2654435761u) ^ (c2 * 805459861u);
    return h % tsize;
}

__device__ __forceinline__ float sigmoidf_(float x) {
    return __fdividef(1.0f, 1.0f + __expf(-x));
}

__device__ __forceinline__ unsigned pack2(float a, float b) {
    __half2 h = __floats2half2_rn(a, b);
    return *(unsigned*)&h;
}

// Zero packed counts (4 MB) + accumulators.
__global__ void __launch_bounds__(TPB) k_zero(unsigned tsize) {
    unsigned i = blockIdx.x * TPB + threadIdx.x;
    uint4* c4 = (uint4*)g_cntp;
    if (i < tsize / 16) c4[i] = make_uint4(0u, 0u, 0u, 0u);
    if (i == 0) { g_sum = 0.0; g_sumsq = 0.0; g_done = 0u; }
}

// Hash 4 points/thread; byte-packed histogram (no-return atomics).
__global__ void __launch_bounds__(TPB) k_hash_count(const int* __restrict__ coords,
                                                    int n, unsigned tsize) {
    int i0 = (blockIdx.x * TPB + threadIdx.x) * 4;
    if (i0 + 3 < n) {
        const int4* cp = (const int4*)(coords + (size_t)i0 * 3);
        int4 a = __ldg(cp + 0);
        int4 b = __ldg(cp + 1);
        int4 c = __ldg(cp + 2);
        unsigned i0x = hash_idx((unsigned)a.x, (unsigned)a.y, (unsigned)a.z, tsize);
        unsigned i1x = hash_idx((unsigned)a.w, (unsigned)b.x, (unsigned)b.y, tsize);
        unsigned i2x = hash_idx((unsigned)b.z, (unsigned)b.w, (unsigned)c.x, tsize);
        unsigned i3x = hash_idx((unsigned)c.y, (unsigned)c.z, (unsigned)c.w, tsize);
        atomicAdd(&g_cntp[i0x >> 2], 1u << ((i0x & 3u) * 8u));
        atomicAdd(&g_cntp[i1x >> 2], 1u << ((i1x & 3u) * 8u));
        atomicAdd(&g_cntp[i2x >> 2], 1u << ((i2x & 3u) * 8u));
        atomicAdd(&g_cntp[i3x >> 2], 1u << ((i3x & 3u) * 8u));
    } else {
        for (int i = i0; i < n; i++) {
            unsigned c0 = (unsigned)coords[3 * i + 0];
            unsigned c1 = (unsigned)coords[3 * i + 1];
            unsigned c2 = (unsigned)coords[3 * i + 2];
            unsigned idx = hash_idx(c0, c1, c2, tsize);
            atomicAdd(&g_cntp[idx >> 2], 1u << ((idx & 3u) * 8u));
        }
    }
}

// Streaming SoA->AoS(fp16) transpose fused with the fp32 stats reduction.
// NEW: threads whose entire 4-entry group is unreferenced (cw==0) skip all
// 14 table loads and all record stores — their stats contribution is exactly
// zero (count-weighted). ~13.5% of groups -> ~32 MB fewer DRAM reads.
// Record layout (16 halves / 32B per entry):
//   pair0: dm0 dm1 | pair1: dm2 q0 | pair2: q1 q2 | pair3: q3 s0
//   pair4: s1 s2   | pair5: h0 h1  | pair6: h2 od | pair7: 0 0
__global__ void __launch_bounds__(TPB) k_transpose(const float* __restrict__ table,
                                                   const float* __restrict__ far_p,
                                                   const int* __restrict__ vs_p,
                                                   unsigned tsize, int n) {
    unsigned t  = threadIdx.x;
    unsigned e4 = blockIdx.x * TPB + t;          // group of 4 entries
    unsigned e  = e4 * 4;

    unsigned cw = g_cntp[e4];
    float s = 0.0f, ss = 0.0f;

    if (cw != 0u) {
        bool bx = (cw & 0xFFu)        != 0u;
        bool by = (cw & 0xFF00u)      != 0u;
        bool bz = (cw & 0xFF0000u)    != 0u;
        bool bw = (cw & 0xFF000000u)  != 0u;

        uint2* rec = (uint2*)(g_rec + (size_t)e * 2);   // 4 uint2 per entry

        // quad 0: rows 0-3 (stats from rows 0-2)
        {
            float4 v0 = __ldcs((const float4*)(table + 0 * (size_t)tsize) + e4);
            float4 v1 = __ldcs((const float4*)(table + 1 * (size_t)tsize) + e4);
            float4 v2 = __ldcs((const float4*)(table + 2 * (size_t)tsize) + e4);
            float4 v3 = __ldcs((const float4*)(table + 3 * (size_t)tsize) + e4);
            float f0 = (float)(cw & 0xFFu);
            float f1 = (float)((cw >> 8) & 0xFFu);
            float f2 = (float)((cw >> 16) & 0xFFu);
            float f3 = (float)(cw >> 24);
            s  = f0 * (v0.x + v1.x + v2.x) + f1 * (v0.y + v1.y + v2.y)
               + f2 * (v0.z + v1.z + v2.z) + f3 * (v0.w + v1.w + v2.w);
            ss = f0 * (v0.x * v0.x + v1.x * v1.x + v2.x * v2.x)
               + f1 * (v0.y * v0.y + v1.y * v1.y + v2.y * v2.y)
               + f2 * (v0.z * v0.z + v1.z * v1.z + v2.z * v2.z)
               + f3 * (v0.w * v0.w + v1.w * v1.w + v2.w * v2.w);
            if (bx) rec[0]  = make_uint2(pack2(v0.x, v1.x), pack2(v2.x, v3.x));
            if (by) rec[4]  = make_uint2(pack2(v0.y, v1.y), pack2(v2.y, v3.y));
            if (bz) rec[8]  = make_uint2(pack2(v0.z, v1.z), pack2(v2.z, v3.z));
            if (bw) rec[12] = make_uint2(pack2(v0.w, v1.w), pack2(v2.w, v3.w));
        }
        // quad 1: rows 4-7
        {
            float4 v0 = __ldcs((const float4*)(table + 4 * (size_t)tsize) + e4);
            float4 v1 = __ldcs((const float4*)(table + 5 * (size_t)tsize) + e4);
            float4 v2 = __ldcs((const float4*)(table + 6 * (size_t)tsize) + e4);
            float4 v3 = __ldcs((const float4*)(table + 7 * (size_t)tsize) + e4);
            if (bx) rec[1]  = make_uint2(pack2(v0.x, v1.x), pack2(v2.x, v3.x));
            if (by) rec[5]  = make_uint2(pack2(v0.y, v1.y), pack2(v2.y, v3.y));
            if (bz) rec[9]  = make_uint2(pack2(v0.z, v1.z), pack2(v2.z, v3.z));
            if (bw) rec[13] = make_uint2(pack2(v0.w, v1.w), pack2(v2.w, v3.w));
        }
        // quad 2: rows 8-11
        {
            float4 v0 = __ldcs((const float4*)(table + 8  * (size_t)tsize) + e4);
            float4 v1 = __ldcs((const float4*)(table + 9  * (size_t)tsize) + e4);
            float4 v2 = __ldcs((const float4*)(table + 10 * (size_t)tsize) + e4);
            float4 v3 = __ldcs((const float4*)(table + 11 * (size_t)tsize) + e4);
            if (bx) rec[2]  = make_uint2(pack2(v0.x, v1.x), pack2(v2.x, v3.x));
            if (by) rec[6]  = make_uint2(pack2(v0.y, v1.y), pack2(v2.y, v3.y));
            if (bz) rec[10] = make_uint2(pack2(v0.z, v1.z), pack2(v2.z, v3.z));
            if (bw) rec[14] = make_uint2(pack2(v0.w, v1.w), pack2(v2.w, v3.w));
        }
        // quad 3: rows 12-13
        {
            float4 v0 = __ldcs((const float4*)(table + 12 * (size_t)tsize) + e4);
            float4 v1 = __ldcs((const float4*)(table + 13 * (size_t)tsize) + e4);
            if (bx) rec[3]  = make_uint2(pack2(v0.x, v1.x), 0u);
            if (by) rec[7]  = make_uint2(pack2(v0.y, v1.y), 0u);
            if (bz) rec[11] = make_uint2(pack2(v0.z, v1.z), 0u);
            if (bw) rec[15] = make_uint2(pack2(v0.w, v1.w), 0u);
        }
    }

    // block stats reduction -> double atomics (all threads participate)
    double ds = (double)s, dss = (double)ss;
    #pragma unroll
    for (int o = 16; o > 0; o >>= 1) {
        ds  += __shfl_down_sync(0xFFFFFFFFu, ds,  o);
        dss += __shfl_down_sync(0xFFFFFFFFu, dss, o);
    }
    __shared__ double sh_s[8], sh_ss[8];
    int lane = t & 31, w = t >> 5;
    if (lane == 0) { sh_s[w] = ds; sh_ss[w] = dss; }
    __syncthreads();
    if (t == 0) {
        double ts = 0.0, tss = 0.0;
        for (int k = 0; k < TPB / 32; k++) { ts += sh_s[k]; tss += sh_ss[k]; }
        atomicAdd(&g_sum, ts);
        atomicAdd(&g_sumsq, tss);
        __threadfence();
        unsigned done = atomicAdd(&g_done, 1u);
        if (done == gridDim.x - 1u) {
            double M    = 3.0 * (double)n;
            double mean = g_sum / M;
            double var  = (g_sumsq - g_sum * g_sum / M) / (M - 1.0);  // ddof=1
            float stdv  = (float)sqrt(var);
            float f     = __ldg(far_p);
            float vs    = (float)__ldg(vs_p);
            float a     = 2.0f * f / vs;
            g_stats = make_float2((float)mean, a / (6.0f * stdv));
        }
    }
}

// Main pass. Each point owns a 20-word smem slot:
//   phase A: 2-lane cooperative fetch of the 32B fp16 record into words 0-7
//   phase B: thread t converts+computes, writes 16 fp32 outputs IN PLACE
//   phase C: coalesced scalar __stcs stores from strided smem
__global__ void __launch_bounds__(TPB, 8) k_main(const int* __restrict__ coords,
                                                 const float* __restrict__ cam,
                                                 const float* __restrict__ far_p,
                                                 const int* __restrict__ vs_p,
                                                 float* __restrict__ out,
                                                 int n, unsigned tsize) {
    __shared__ int sh_co[TPB * 3];                        // 3 KB coords
    __shared__ __align__(16) float slot[TPB * 20];        // 20 KB slots

    int t  = threadIdx.x;
    int p0 = blockIdx.x * TPB;
    int blk = min(TPB, n - p0);

    if (blk == TPB) {
        if (t < TPB * 3 / 4)
            ((int4*)sh_co)[t] = __ldg((const int4*)(coords + (size_t)p0 * 3) + t);
    } else {
        for (int k = t; k < blk * 3; k += TPB)
            sh_co[k] = coords[(size_t)p0 * 3 + k];
    }
    __syncthreads();

    // phase A: pair of lanes per point fetch the 32B record
    int gid = t >> 1, q = t & 1;
    #pragma unroll
    for (int it = 0; it < 2; it++) {
        int pl = it * 128 + gid;
        if (pl < blk) {
            unsigned idx = hash_idx((unsigned)sh_co[pl * 3 + 0],
                                    (unsigned)sh_co[pl * 3 + 1],
                                    (unsigned)sh_co[pl * 3 + 2], tsize);
            *(uint4*)(slot + pl * 20 + q * 4) = __ldg(g_rec + (size_t)idx * 2 + q);
        }
    }
    __syncthreads();

    if (t < blk) {
        float* sl = slot + t * 20;
        const __half2* hp = (const __half2*)sl;
        float2 p0v = __half22float2(hp[0]);   // dm0 dm1
        float2 p1v = __half22float2(hp[1]);   // dm2 q0
        float2 p2v = __half22float2(hp[2]);   // q1 q2
        float2 p3v = __half22float2(hp[3]);   // q3 s0
        float2 p4v = __half22float2(hp[4]);   // s1 s2
        float2 p5v = __half22float2(hp[5]);   // h0 h1
        float2 p6v = __half22float2(hp[6]);   // h2 od

        float f  = __ldg(far_p);
        float vs = (float)__ldg(vs_p);
        float a  = 2.0f * f / vs;
        float off = -f + f / vs;
        float2 st = g_stats;

        int c0 = sh_co[t * 3 + 0];
        int c1 = sh_co[t * 3 + 1];
        int c2 = sh_co[t * 3 + 2];

        sl[0] = (p0v.x - st.x) * st.y + (float)c0 * a + __ldg(cam + 0) + off;
        sl[1] = (p0v.y - st.x) * st.y + (float)c1 * a + __ldg(cam + 1) + off;
        sl[2] = (p1v.x - st.x) * st.y + (float)c2 * a + __ldg(cam + 2) + off;

        float q0 = p1v.y, q1 = p2v.x, q2 = p2v.y, q3 = p3v.x;
        float rn = rsqrtf(q0 * q0 + q1 * q1 + q2 * q2 + q3 * q3);
        float r = q0 * rn, x = q1 * rn, y = q2 * rn, z = q3 * rn;
        float R00 = 1.0f - 2.0f * (y * y + z * z);
        float R01 = 2.0f * (x * y - r * z);
        float R02 = 2.0f * (x * z + r * y);
        float R10 = 2.0f * (x * y + r * z);
        float R11 = 1.0f - 2.0f * (x * x + z * z);
        float R12 = 2.0f * (y * z - r * x);
        float R20 = 2.0f * (x * z - r * y);
        float R21 = 2.0f * (y * z + r * x);
        float R22 = 1.0f - 2.0f * (x * x + y * y);

        float sc0 = sigmoidf_(p3v.y) * a;
        float sc1 = sigmoidf_(p4v.x) * a;
        float sc2 = sigmoidf_(p4v.y) * a;
        float v0 = sc0 * sc0, v1 = sc1 * sc1, v2 = sc2 * sc2;

        float c01 = R00 * R10 * v0 + R01 * R11 * v1 + R02 * R12 * v2;
        float c02 = R00 * R20 * v0 + R01 * R21 * v1 + R02 * R22 * v2;
        float c12 = R10 * R20 * v0 + R11 * R21 * v1 + R12 * R22 * v2;
        sl[3]  = R00 * R00 * v0 + R01 * R01 * v1 + R02 * R02 * v2;
        sl[4]  = c01; sl[5] = c02;
        sl[6]  = c01;
        sl[7]  = R10 * R10 * v0 + R11 * R11 * v1 + R12 * R12 * v2;
        sl[8]  = c12;
        sl[9]  = c02; sl[10] = c12;
        sl[11] = R20 * R20 * v0 + R21 * R21 * v1 + R22 * R22 * v2;

        sl[12] = p5v.x;
        sl[13] = p5v.y;
        sl[14] = p6v.x;
        sl[15] = sigmoidf_(p6v.y - 4.0f);
    }
    __syncthreads();

    float* means = out;
    float* cov   = out + 3  * (size_t)n;
    float* harm  = out + 12 * (size_t)n;
    float* opac  = out + 15 * (size_t)n;

    for (int k = t; k < blk * 3; k += TPB)
        __stcs(means + (size_t)p0 * 3 + k, slot[(k / 3) * 20 + (k % 3)]);
    for (int k = t; k < blk * 9; k += TPB)
        __stcs(cov + (size_t)p0 * 9 + k, slot[(k / 9) * 20 + 3 + (k % 9)]);
    for (int k = t; k < blk * 3; k += TPB)
        __stcs(harm + (size_t)p0 * 3 + k, slot[(k / 3) * 20 + 12 + (k % 3)]);
    if (t < blk)
        __stcs(opac + p0 + t, slot[t * 20 + 15]);
}

extern "C" void kernel_launch(void* const* d_in, const int* in_sizes, int n_in,
                              void* d_out, int out_size) {
    const int*   coords = (const int*)d_in[0];
    const float* table  = (const float*)d_in[1];
    const float* cam    = (const float*)d_in[2];
    const float* far_p  = (const float*)d_in[3];
    const int*   vs_p   = (const int*)d_in[4];
    float*       out    = (float*)d_out;

    int n = in_sizes[0] / 3;
    unsigned tsize = (unsigned)(in_sizes[1] / 14);   // 4194304 for this problem

    int pblocks = (n + TPB - 1) / TPB;
    int hblocks = (n / 4 + TPB - 1) / TPB;
    int zblocks = (int)((tsize / 16 + TPB - 1) / TPB);
    int tblocks = (int)((tsize / 4 + TPB - 1) / TPB);

    k_zero      <<<zblocks, TPB>>>(tsize);
    k_hash_count<<<hblocks, TPB>>>(coords, n, tsize);
    k_transpose <<<tblocks, TPB>>>(table, far_p, vs_p, tsize, n);
    k_main      <<<pblocks, TPB>>>(coords, cam, far_p, vs_p, out, n, tsize);
}